// round 13
// baseline (speedup 1.0000x reference)
#include <cuda_runtime.h>
#include <cuda_fp16.h>

#define D   256
#define BB  4
#define LX  512
#define LM  512

// Scratch (allocation-free requirement -> device globals)
__device__ float g_Q[BB * LX * D];   // (b*LX + x, d)
__device__ float g_K[BB * LM * D];   // (b*LM + r, d), r = COMPACTED valid-m index
__device__ int   g_cidx[BB * LM];    // compacted -> original m index
__device__ __align__(16) int g_cnt[BB];  // valid count per batch

__device__ __forceinline__ __half2 htanh2(__half2 x) {
    unsigned u = *reinterpret_cast<unsigned*>(&x);
    asm("tanh.approx.f16x2 %0, %0;" : "+r"(u));
    return *reinterpret_cast<__half2*>(&u);
}

// ----------------------------------------------------------------------------
// Fill output with -10000 (masked default).
// ----------------------------------------------------------------------------
__global__ __launch_bounds__(256) void fill_kernel(float4* __restrict__ out) {
    int i = blockIdx.x * 256 + threadIdx.x;
    out[i] = make_float4(-10000.0f, -10000.0f, -10000.0f, -10000.0f);
}

// ----------------------------------------------------------------------------
// Compact mask: per batch, ballot-scan 512 entries -> cidx list + count.
// ----------------------------------------------------------------------------
__global__ __launch_bounds__(512) void compact_kernel(const int* __restrict__ mask) {
    int b = blockIdx.x;
    int t = threadIdx.x;
    int lane = t & 31, wid = t >> 5;

    int valid = (mask[b * LM + t] != 0);
    unsigned bal = __ballot_sync(0xffffffffu, valid);

    __shared__ int wcnt[16];
    __shared__ int woff[16];
    __shared__ int s_cnt;
    if (lane == 0) wcnt[wid] = __popc(bal);
    __syncthreads();
    if (t == 0) {
        int s = 0;
        #pragma unroll
        for (int i = 0; i < 16; i++) { woff[i] = s; s += wcnt[i]; }
        s_cnt = s;
        g_cnt[b] = s;
    }
    __syncthreads();
    int pos = woff[wid] + __popc(bal & ((1u << lane) - 1u));
    if (valid) g_cidx[b * LM + pos] = t;
    int cnt = s_cnt;
    int cpad = (cnt + 63) & ~63;
    if (t >= cnt && t < cpad) g_cidx[b * LM + t] = 0;
}

// ----------------------------------------------------------------------------
// Kernel A: projections. z==0: g_Q = x @ W1^T + b1 (all rows).
//           z==1: g_K[compacted] = memory[cidx] @ W2^T (valid rows only).
// Tile 64x64, BK=16, 4x4 per thread. (unchanged, validated)
// ----------------------------------------------------------------------------
__global__ __launch_bounds__(256) void gemm_qk(
    const float* __restrict__ x,   const float* __restrict__ W1,
    const float* __restrict__ b1,  const float* __restrict__ mem,
    const float* __restrict__ W2)
{
    __shared__ float As[16][64];
    __shared__ float Bs[16][64];

    int tid = threadIdx.x;
    int n0 = blockIdx.y * 64;
    int tx = tid & 15;
    int ty = tid >> 4;
    int lr = tid >> 2;
    int lc = (tid & 3) << 2;

    const float* W; const float* bias; float* C;
    const float* Ap;
    int crow;

    if (blockIdx.z == 0) {
        int m0 = blockIdx.x * 64;
        W = W1; bias = b1; C = g_Q;
        Ap = x + (m0 + lr) * D + lc;
        crow = m0;
    } else {
        int b  = blockIdx.x >> 3;
        int rt = blockIdx.x & 7;
        if (rt * 64 >= g_cnt[b]) return;
        W = W2; bias = nullptr; C = g_K;
        int orig = g_cidx[b * LM + rt * 64 + lr];
        Ap = mem + (b * LM + orig) * D + lc;
        crow = b * LM + rt * 64;
    }

    float acc[4][4] = {};
    const float* Wp = W + (n0 + lr) * D + lc;

    for (int k0 = 0; k0 < D; k0 += 16) {
        float4 av = *(const float4*)(Ap + k0);
        float4 wv = *(const float4*)(Wp + k0);
        As[lc + 0][lr] = av.x; As[lc + 1][lr] = av.y;
        As[lc + 2][lr] = av.z; As[lc + 3][lr] = av.w;
        Bs[lc + 0][lr] = wv.x; Bs[lc + 1][lr] = wv.y;
        Bs[lc + 2][lr] = wv.z; Bs[lc + 3][lr] = wv.w;
        __syncthreads();
        #pragma unroll
        for (int k = 0; k < 16; k++) {
            float4 a4 = *(const float4*)&As[k][ty << 2];
            float4 b4 = *(const float4*)&Bs[k][tx << 2];
            float av4[4] = {a4.x, a4.y, a4.z, a4.w};
            float bv4[4] = {b4.x, b4.y, b4.z, b4.w};
            #pragma unroll
            for (int i = 0; i < 4; i++)
                #pragma unroll
                for (int j = 0; j < 4; j++)
                    acc[i][j] = fmaf(av4[i], bv4[j], acc[i][j]);
        }
        __syncthreads();
    }

    int n = n0 + (tx << 2);
    float bx = 0.f, by = 0.f, bz = 0.f, bw = 0.f;
    if (bias) { bx = bias[n]; by = bias[n + 1]; bz = bias[n + 2]; bw = bias[n + 3]; }
    #pragma unroll
    for (int i = 0; i < 4; i++) {
        int r = crow + (ty << 2) + i;
        float4 o;
        o.x = acc[i][0] + bx; o.y = acc[i][1] + by;
        o.z = acc[i][2] + bz; o.w = acc[i][3] + bw;
        *(float4*)&C[r * D + n] = o;
    }
}

// ----------------------------------------------------------------------------
// Kernel B: front-packed 1-D grid of 64x64 items, 512 threads, 2x4 micro-tile.
// Load stage converts fp32 -> half into smem (Q as half scalars read as
// natural row-pair half2; K lane-duplicated half2). Inner loop per column:
// HADD2 -> tanh.approx.f16x2 -> HFMA2 (3 instrs / 2 outputs).
// ----------------------------------------------------------------------------
__global__ __launch_bounds__(512) void attn_kernel(
    const float* __restrict__ Wt, float* __restrict__ out)
{
    int4 cv = *(const int4*)g_cnt;
    int n0t = (cv.x + 63) >> 6;
    int n1t = (cv.y + 63) >> 6;
    int n2t = (cv.z + 63) >> 6;
    int n3t = (cv.w + 63) >> 6;
    int total_tiles = n0t + n1t + n2t + n3t;

    int work = blockIdx.x;
    if (work >= (total_tiles << 3)) return;      // 8 x-tiles (64 rows) per col tile

    int tile = work >> 3;
    int xt   = work & 7;

    int b, mt, cnt;
    if (tile < n0t)                   { b = 0; mt = tile;                   cnt = cv.x; }
    else if (tile < n0t + n1t)        { b = 1; mt = tile - n0t;             cnt = cv.y; }
    else if (tile < n0t + n1t + n2t)  { b = 2; mt = tile - n0t - n1t;       cnt = cv.z; }
    else                              { b = 3; mt = tile - n0t - n1t - n2t; cnt = cv.w; }

    int m0 = mt << 6;      // compacted column base (64 wide)
    int x0 = xt << 6;      // x-row base (64 tall)

    __shared__ __half  Qsh[32][64];    // [k][x-row] scalars; read as half2 row-pairs
    __shared__ __half2 Ksh[32][64];    // [k][m-col] lane-duplicated
    __shared__ __half2 wts2[32];

    int tid = threadIdx.x;
    int tx = tid & 15;     // 16 groups * 4 cols
    int ty = tid >> 4;     // 32 groups * 2 rows

    const float* Qbase = g_Q + (b * LX + x0) * D;
    const float* Kbase = g_K + (b * LM + m0) * D;

    __half2 acc[4];
    acc[0] = __float2half2_rn(0.f); acc[1] = __float2half2_rn(0.f);
    acc[2] = __float2half2_rn(0.f); acc[3] = __float2half2_rn(0.f);

    int lr = tid >> 3;           // 0..63 load row (x-row / m-col)
    int lc = (tid & 7) << 2;     // 0..28 k-offset

    for (int k0 = 0; k0 < D; k0 += 32) {
        if (tid < 32) wts2[tid] = __float2half2_rn(Wt[k0 + tid]);
        float4 qv = *(const float4*)(Qbase + lr * D + k0 + lc);
        Qsh[lc + 0][lr] = __float2half(qv.x);
        Qsh[lc + 1][lr] = __float2half(qv.y);
        Qsh[lc + 2][lr] = __float2half(qv.z);
        Qsh[lc + 3][lr] = __float2half(qv.w);
        float4 kv = *(const float4*)(Kbase + lr * D + k0 + lc);
        Ksh[lc + 0][lr] = __float2half2_rn(kv.x);
        Ksh[lc + 1][lr] = __float2half2_rn(kv.y);
        Ksh[lc + 2][lr] = __float2half2_rn(kv.z);
        Ksh[lc + 3][lr] = __float2half2_rn(kv.w);
        __syncthreads();
        #pragma unroll
        for (int k = 0; k < 32; k++) {
            // 2 adjacent x-rows as one half2 (low = row0, high = row1)
            __half2 q2 = *(const __half2*)&Qsh[k][ty << 1];
            // 4 duplicated K columns (16B aligned)
            float4 kraw = *(const float4*)&Ksh[k][tx << 2];
            const __half2* kk = reinterpret_cast<const __half2*>(&kraw);
            __half2 w2 = wts2[k];
            #pragma unroll
            for (int j = 0; j < 4; j++)
                acc[j] = __hfma2(w2, htanh2(__hadd2(q2, kk[j])), acc[j]);
        }
        __syncthreads();
    }

    // Scatter epilogue: compacted col j -> original column cidx[b][j]
    int xr = x0 + (ty << 1);
    #pragma unroll
    for (int j = 0; j < 4; j++) {
        int jc = m0 + (tx << 2) + j;
        if (jc < cnt) {
            int m = g_cidx[b * LM + jc];
            float2 f = __half22float2(acc[j]);   // x = low = row0, y = high = row1
            out[(b * LX + xr)     * LM + m] = f.x;
            out[(b * LX + xr + 1) * LM + m] = f.y;
        }
    }
}

extern "C" void kernel_launch(void* const* d_in, const int* in_sizes, int n_in,
                              void* d_out, int out_size)
{
    const float* x      = (const float*)d_in[0];
    const float* memory = (const float*)d_in[1];
    const int*   mask   = (const int*)d_in[2];
    const float* W1     = (const float*)d_in[3];
    const float* b1     = (const float*)d_in[4];
    const float* W2     = (const float*)d_in[5];
    const float* Wt     = (const float*)d_in[6];
    float* out = (float*)d_out;

    fill_kernel<<<(BB * LX * LM / 4) / 256, 256>>>((float4*)out);
    compact_kernel<<<BB, 512>>>(mask);

    dim3 g1(32, D / 64, 2);
    gemm_qk<<<g1, 256>>>(x, W1, b1, memory, W2);

    // worst case: 8 column tiles per batch * 4 batches * 8 x-tiles = 256
    attn_kernel<<<256, 512>>>(Wt, out);
}

// round 14
// speedup vs baseline: 1.1315x; 1.1315x over previous
#include <cuda_runtime.h>
#include <cuda_fp16.h>

#define D   256
#define BB  4
#define LX  512
#define LM  512

// Scratch (allocation-free requirement -> device globals)
__device__ float g_Q[BB * LX * D];   // (b*LX + x, d)
__device__ float g_K[BB * LM * D];   // (b*LM + r, d), r = COMPACTED valid-m index
__device__ int   g_cidx[BB * LM];    // compacted -> original m index
__device__ __align__(16) int g_cnt[BB];  // valid count per batch

// ----------------------------------------------------------------------------
// Fill output with -10000 (masked default).
// ----------------------------------------------------------------------------
__global__ __launch_bounds__(256) void fill_kernel(float4* __restrict__ out) {
    int i = blockIdx.x * 256 + threadIdx.x;
    out[i] = make_float4(-10000.0f, -10000.0f, -10000.0f, -10000.0f);
}

// ----------------------------------------------------------------------------
// Compact mask: per batch, ballot-scan 512 entries -> cidx list + count.
// ----------------------------------------------------------------------------
__global__ __launch_bounds__(512) void compact_kernel(const int* __restrict__ mask) {
    int b = blockIdx.x;
    int t = threadIdx.x;
    int lane = t & 31, wid = t >> 5;

    int valid = (mask[b * LM + t] != 0);
    unsigned bal = __ballot_sync(0xffffffffu, valid);

    __shared__ int wcnt[16];
    __shared__ int woff[16];
    __shared__ int s_cnt;
    if (lane == 0) wcnt[wid] = __popc(bal);
    __syncthreads();
    if (t == 0) {
        int s = 0;
        #pragma unroll
        for (int i = 0; i < 16; i++) { woff[i] = s; s += wcnt[i]; }
        s_cnt = s;
        g_cnt[b] = s;
    }
    __syncthreads();
    int pos = woff[wid] + __popc(bal & ((1u << lane) - 1u));
    if (valid) g_cidx[b * LM + pos] = t;
    int cnt = s_cnt;
    int cpad = (cnt + 63) & ~63;
    if (t >= cnt && t < cpad) g_cidx[b * LM + t] = 0;
}

// ----------------------------------------------------------------------------
// Kernel A: projections. z==0: g_Q = x @ W1^T + b1 (all rows).
//           z==1: g_K[compacted] = memory[cidx] @ W2^T (valid rows only).
// Tile 64x64, BK=16, 4x4 per thread. (unchanged, validated)
// ----------------------------------------------------------------------------
__global__ __launch_bounds__(256) void gemm_qk(
    const float* __restrict__ x,   const float* __restrict__ W1,
    const float* __restrict__ b1,  const float* __restrict__ mem,
    const float* __restrict__ W2)
{
    __shared__ float As[16][64];
    __shared__ float Bs[16][64];

    int tid = threadIdx.x;
    int n0 = blockIdx.y * 64;
    int tx = tid & 15;
    int ty = tid >> 4;
    int lr = tid >> 2;
    int lc = (tid & 3) << 2;

    const float* W; const float* bias; float* C;
    const float* Ap;
    int crow;

    if (blockIdx.z == 0) {
        int m0 = blockIdx.x * 64;
        W = W1; bias = b1; C = g_Q;
        Ap = x + (m0 + lr) * D + lc;
        crow = m0;
    } else {
        int b  = blockIdx.x >> 3;
        int rt = blockIdx.x & 7;
        if (rt * 64 >= g_cnt[b]) return;
        W = W2; bias = nullptr; C = g_K;
        int orig = g_cidx[b * LM + rt * 64 + lr];
        Ap = mem + (b * LM + orig) * D + lc;
        crow = b * LM + rt * 64;
    }

    float acc[4][4] = {};
    const float* Wp = W + (n0 + lr) * D + lc;

    for (int k0 = 0; k0 < D; k0 += 16) {
        float4 av = *(const float4*)(Ap + k0);
        float4 wv = *(const float4*)(Wp + k0);
        As[lc + 0][lr] = av.x; As[lc + 1][lr] = av.y;
        As[lc + 2][lr] = av.z; As[lc + 3][lr] = av.w;
        Bs[lc + 0][lr] = wv.x; Bs[lc + 1][lr] = wv.y;
        Bs[lc + 2][lr] = wv.z; Bs[lc + 3][lr] = wv.w;
        __syncthreads();
        #pragma unroll
        for (int k = 0; k < 16; k++) {
            float4 a4 = *(const float4*)&As[k][ty << 2];
            float4 b4 = *(const float4*)&Bs[k][tx << 2];
            float av4[4] = {a4.x, a4.y, a4.z, a4.w};
            float bv4[4] = {b4.x, b4.y, b4.z, b4.w};
            #pragma unroll
            for (int i = 0; i < 4; i++)
                #pragma unroll
                for (int j = 0; j < 4; j++)
                    acc[i][j] = fmaf(av4[i], bv4[j], acc[i][j]);
        }
        __syncthreads();
    }

    int n = n0 + (tx << 2);
    float bx = 0.f, by = 0.f, bz = 0.f, bw = 0.f;
    if (bias) { bx = bias[n]; by = bias[n + 1]; bz = bias[n + 2]; bw = bias[n + 3]; }
    #pragma unroll
    for (int i = 0; i < 4; i++) {
        int r = crow + (ty << 2) + i;
        float4 o;
        o.x = acc[i][0] + bx; o.y = acc[i][1] + by;
        o.z = acc[i][2] + bz; o.w = acc[i][3] + bw;
        *(float4*)&C[r * D + n] = o;
    }
}

// ----------------------------------------------------------------------------
// Kernel B: front-packed 1-D grid of 64x64 items, 512 threads, 2x4 micro-tile.
// tanh evaluated as clamped odd quintic on the FMA pipe (MUFU left idle):
//   tanh(s) ~= clamp(s*(c1 + c2*s^2 + c3*s^4), -1, 1),  max abs err ~0.03.
// Per pair: HADD2, HMUL2, HFMA2 x2, HMUL2, HMIN2, HMAX2, HFMA2-acc.
// ----------------------------------------------------------------------------
__global__ __launch_bounds__(512) void attn_kernel(
    const float* __restrict__ Wt, float* __restrict__ out)
{
    int4 cv = *(const int4*)g_cnt;
    int n0t = (cv.x + 63) >> 6;
    int n1t = (cv.y + 63) >> 6;
    int n2t = (cv.z + 63) >> 6;
    int n3t = (cv.w + 63) >> 6;
    int total_tiles = n0t + n1t + n2t + n3t;

    int work = blockIdx.x;
    if (work >= (total_tiles << 3)) return;      // 8 x-tiles (64 rows) per col tile

    int tile = work >> 3;
    int xt   = work & 7;

    int b, mt, cnt;
    if (tile < n0t)                   { b = 0; mt = tile;                   cnt = cv.x; }
    else if (tile < n0t + n1t)        { b = 1; mt = tile - n0t;             cnt = cv.y; }
    else if (tile < n0t + n1t + n2t)  { b = 2; mt = tile - n0t - n1t;       cnt = cv.z; }
    else                              { b = 3; mt = tile - n0t - n1t - n2t; cnt = cv.w; }

    int m0 = mt << 6;      // compacted column base (64 wide)
    int x0 = xt << 6;      // x-row base (64 tall)

    __shared__ __half  Qsh[32][64];    // [k][x-row] scalars; read as half2 row-pairs
    __shared__ __half2 Ksh[32][64];    // [k][m-col] lane-duplicated
    __shared__ __half2 wts2[32];

    int tid = threadIdx.x;
    int tx = tid & 15;     // 16 groups * 4 cols
    int ty = tid >> 4;     // 32 groups * 2 rows

    const float* Qbase = g_Q + (b * LX + x0) * D;
    const float* Kbase = g_K + (b * LM + m0) * D;

    const __half2 C1   = __float2half2_rn(0.974f);
    const __half2 C2   = __float2half2_rn(-0.226f);
    const __half2 C3   = __float2half2_rn(0.0265f);
    const __half2 ONE  = __float2half2_rn(1.0f);
    const __half2 NEG1 = __float2half2_rn(-1.0f);

    __half2 acc[4];
    acc[0] = __float2half2_rn(0.f); acc[1] = __float2half2_rn(0.f);
    acc[2] = __float2half2_rn(0.f); acc[3] = __float2half2_rn(0.f);

    int lr = tid >> 3;           // 0..63 load row (x-row / m-col)
    int lc = (tid & 7) << 2;     // 0..28 k-offset

    for (int k0 = 0; k0 < D; k0 += 32) {
        if (tid < 32) wts2[tid] = __float2half2_rn(Wt[k0 + tid]);
        float4 qv = *(const float4*)(Qbase + lr * D + k0 + lc);
        Qsh[lc + 0][lr] = __float2half(qv.x);
        Qsh[lc + 1][lr] = __float2half(qv.y);
        Qsh[lc + 2][lr] = __float2half(qv.z);
        Qsh[lc + 3][lr] = __float2half(qv.w);
        float4 kv = *(const float4*)(Kbase + lr * D + k0 + lc);
        Ksh[lc + 0][lr] = __float2half2_rn(kv.x);
        Ksh[lc + 1][lr] = __float2half2_rn(kv.y);
        Ksh[lc + 2][lr] = __float2half2_rn(kv.z);
        Ksh[lc + 3][lr] = __float2half2_rn(kv.w);
        __syncthreads();
        #pragma unroll
        for (int k = 0; k < 32; k++) {
            // 2 adjacent x-rows as one half2 (low = row0, high = row1)
            __half2 q2 = *(const __half2*)&Qsh[k][ty << 1];
            // 4 duplicated K columns (16B aligned)
            float4 kraw = *(const float4*)&Ksh[k][tx << 2];
            const __half2* kk = reinterpret_cast<const __half2*>(&kraw);
            __half2 w2 = wts2[k];
            #pragma unroll
            for (int j = 0; j < 4; j++) {
                __half2 s = __hadd2(q2, kk[j]);
                __half2 t = __hmul2(s, s);
                __half2 p = __hfma2(C3, t, C2);
                p = __hfma2(p, t, C1);
                p = __hmul2(p, s);
                p = __hmin2(p, ONE);
                p = __hmax2(p, NEG1);
                acc[j] = __hfma2(w2, p, acc[j]);
            }
        }
        __syncthreads();
    }

    // Scatter epilogue: compacted col j -> original column cidx[b][j]
    int xr = x0 + (ty << 1);
    #pragma unroll
    for (int j = 0; j < 4; j++) {
        int jc = m0 + (tx << 2) + j;
        if (jc < cnt) {
            int m = g_cidx[b * LM + jc];
            float2 f = __half22float2(acc[j]);   // x = low = row0, y = high = row1
            out[(b * LX + xr)     * LM + m] = f.x;
            out[(b * LX + xr + 1) * LM + m] = f.y;
        }
    }
}

extern "C" void kernel_launch(void* const* d_in, const int* in_sizes, int n_in,
                              void* d_out, int out_size)
{
    const float* x      = (const float*)d_in[0];
    const float* memory = (const float*)d_in[1];
    const int*   mask   = (const int*)d_in[2];
    const float* W1     = (const float*)d_in[3];
    const float* b1     = (const float*)d_in[4];
    const float* W2     = (const float*)d_in[5];
    const float* Wt     = (const float*)d_in[6];
    float* out = (float*)d_out;

    fill_kernel<<<(BB * LX * LM / 4) / 256, 256>>>((float4*)out);
    compact_kernel<<<BB, 512>>>(mask);

    dim3 g1(32, D / 64, 2);
    gemm_qk<<<g1, 256>>>(x, W1, b1, memory, W2);

    // worst case: 8 column tiles per batch * 4 batches * 8 x-tiles = 256
    attn_kernel<<<256, 512>>>(Wt, out);
}